// round 9
// baseline (speedup 1.0000x reference)
#include <cuda_runtime.h>

#define NN 100000
#define EE 1600000

typedef unsigned long long u64;

// ---------------- scratch (static __device__, no allocation) ----------------
__device__ float g_xw[NN * 40];      // per-layer xw (concat heads)
__device__ float g_lin[NN * 40];     // skip linear output (incl lb)
__device__ float g_h[NN * 40];       // current hidden state
__device__ float g_asrc[NN * 8];     // per-head src scores (padded to 8)
__device__ float g_adst[NN * 8];
__device__ float g_aggs[NN * 240];   // layer-3 per-head aggregated h2 [N,6,40]
__device__ float g_vsrc[240];        // W3[:,h,:]@as3[h]  -> [6,40]
__device__ float g_vdst[240];
__device__ float g_wm[280 * 128];    // fused final weight [280,128pad]
__device__ float g_biasc[128];       // b3 + lb3

// CSR scratch
__device__ int g_deg[NN];
__device__ int g_incl[NN];
__device__ int g_bsum[256];
__device__ int g_boff[256];
__device__ int g_rowstart[NN + 1];
__device__ int g_cursor[NN];
__device__ int g_csr_src[EE];

// degree-sorted node order (warp load balancing)
__device__ int g_dhist[256];
__device__ int g_dcur[256];
__device__ int g_order[NN];

__device__ __forceinline__ float lrelu(float v) { return v > 0.f ? v : 0.2f * v; }
__device__ __forceinline__ float elu1(float v) { return v > 0.f ? v : (__expf(v) - 1.f); }

// ================= CSR build =================
__global__ void zero_deg() {
  int i = blockIdx.x * 256 + threadIdx.x;
  if (i < NN) g_deg[i] = 0;
  if (blockIdx.x == 0) g_dhist[threadIdx.x] = 0;
}
__global__ void hist_k(const int* __restrict__ ei) {
  int e = blockIdx.x * 256 + threadIdx.x;
  if (e < EE) atomicAdd(&g_deg[ei[EE + e]], 1);
}
__global__ void scan1_k() {  // 196 blocks x 512
  __shared__ int sb[512];
  int t = threadIdx.x;
  int i = blockIdx.x * 512 + t;
  int v = (i < NN) ? g_deg[i] : 0;
  sb[t] = v;
  __syncthreads();
  for (int off = 1; off < 512; off <<= 1) {
    int x = (t >= off) ? sb[t - off] : 0;
    __syncthreads();
    sb[t] += x;
    __syncthreads();
  }
  if (i < NN) g_incl[i] = sb[t];
  if (t == 511) g_bsum[blockIdx.x] = sb[511];
}
__global__ void scan2_k(int nb) {  // 1 block, 256 threads
  __shared__ int sb[256];
  int t = threadIdx.x;
  int own = (t < nb) ? g_bsum[t] : 0;
  sb[t] = own;
  __syncthreads();
  for (int off = 1; off < 256; off <<= 1) {
    int x = (t >= off) ? sb[t - off] : 0;
    __syncthreads();
    sb[t] += x;
    __syncthreads();
  }
  g_boff[t] = sb[t] - own;  // exclusive
}
__global__ void scan3_k() {
  int i = blockIdx.x * 256 + threadIdx.x;
  if (i < NN) {
    int rs = g_incl[i] - g_deg[i] + g_boff[i / 512];
    g_rowstart[i] = rs;
    g_cursor[i] = rs;
    if (i == NN - 1) g_rowstart[NN] = EE;
  }
}
__global__ void scatter_k(const int* __restrict__ ei) {
  int e = blockIdx.x * 256 + threadIdx.x;
  if (e < EE) {
    int s = ei[e], d = ei[EE + e];
    int p = atomicAdd(&g_cursor[d], 1);
    g_csr_src[p] = s;
  }
}

// ================= degree counting-sort (node order for balance) =================
__global__ void dhist_k() {
  int i = blockIdx.x * 256 + threadIdx.x;
  if (i < NN) atomicAdd(&g_dhist[min(g_deg[i], 255)], 1);
}
__global__ void dscan_k() {  // 1 block 256, exclusive
  __shared__ int sb[256];
  int t = threadIdx.x;
  int v = g_dhist[t];
  sb[t] = v;
  __syncthreads();
  for (int off = 1; off < 256; off <<= 1) {
    int x = (t >= off) ? sb[t - off] : 0;
    __syncthreads();
    sb[t] += x;
    __syncthreads();
  }
  g_dcur[t] = sb[t] - v;
}
__global__ void dscatter_k() {
  int i = blockIdx.x * 256 + threadIdx.x;
  if (i < NN) {
    int b = min(g_deg[i], 255);
    int p = atomicAdd(&g_dcur[b], 1);
    g_order[p] = i;
  }
}

// ---------------- node GEMM: xw = x@W, lin = x@lw+lb, scores ----
template <int KDIM>
__global__ __launch_bounds__(128) void node_gemm_k(
    const float* __restrict__ x, const float* __restrict__ W,
    const float* __restrict__ lw, const float* __restrict__ lb,
    const float* __restrict__ as_, const float* __restrict__ ad_) {
  __shared__ float sW[KDIM * 80];
  __shared__ float sX[32 * (KDIM + 1)];
  __shared__ float sAs[40], sAd[40], sLb[40];
  const int t = threadIdx.x;
  for (int i = t; i < KDIM * 80; i += 128) {
    int k = i / 80, j = i % 80;
    sW[i] = (j < 40) ? W[k * 40 + j] : lw[k * 40 + (j - 40)];
  }
  const int nb = blockIdx.x * 32;
  for (int i = t; i < 32 * KDIM; i += 128) {
    int r = i / KDIM, k = i % KDIM;
    sX[r * (KDIM + 1) + k] = x[(nb + r) * KDIM + k];
  }
  if (t < 40) { sAs[t] = as_[t]; sAd[t] = ad_[t]; sLb[t] = lb[t]; }
  __syncthreads();

  const int row = t >> 2, cg = t & 3, c0 = cg * 20;
  float acc[20];
#pragma unroll
  for (int j = 0; j < 20; j++) acc[j] = 0.f;
#pragma unroll 5
  for (int k = 0; k < KDIM; k++) {
    float a = sX[row * (KDIM + 1) + k];
    const float4* w4 = reinterpret_cast<const float4*>(&sW[k * 80 + c0]);
#pragma unroll
    for (int q = 0; q < 5; q++) {
      float4 w = w4[q];
      acc[4 * q + 0] += a * w.x;
      acc[4 * q + 1] += a * w.y;
      acc[4 * q + 2] += a * w.z;
      acc[4 * q + 3] += a * w.w;
    }
  }
  const int n = nb + row;
  if (cg < 2) {
    float4* o = reinterpret_cast<float4*>(&g_xw[n * 40 + c0]);
#pragma unroll
    for (int q = 0; q < 5; q++)
      o[q] = make_float4(acc[4 * q], acc[4 * q + 1], acc[4 * q + 2], acc[4 * q + 3]);
    float s0 = 0.f, s1 = 0.f, d0 = 0.f, d1 = 0.f;
#pragma unroll
    for (int j = 0; j < 10; j++) {
      s0 += acc[j] * sAs[c0 + j];           d0 += acc[j] * sAd[c0 + j];
      s1 += acc[10 + j] * sAs[c0 + 10 + j]; d1 += acc[10 + j] * sAd[c0 + 10 + j];
    }
    const int h0 = 2 * cg;
    g_asrc[n * 8 + h0] = s0;      g_asrc[n * 8 + h0 + 1] = s1;
    g_adst[n * 8 + h0] = d0;      g_adst[n * 8 + h0 + 1] = d1;
  } else {
    const int lc = c0 - 40;
    float4* o = reinterpret_cast<float4*>(&g_lin[n * 40 + lc]);
#pragma unroll
    for (int q = 0; q < 5; q++)
      o[q] = make_float4(acc[4 * q] + sLb[lc + 4 * q], acc[4 * q + 1] + sLb[lc + 4 * q + 1],
                         acc[4 * q + 2] + sLb[lc + 4 * q + 2], acc[4 * q + 3] + sLb[lc + 4 * q + 3]);
  }
}

// ================= fused CSR aggregation, layers 1/2 (4 heads) =================
// 10-lane groups, 3 per warp. dst taken from degree-sorted g_order so the 3
// rows in a warp have near-equal length. Two-deep pipeline: src index is
// prefetched one full iteration before its score/feature loads issue.
__global__ __launch_bounds__(320) void csr_agg_l12(const float* __restrict__ bias) {
  const int t = threadIdx.x;
  const int lane = t & 31, warp = t >> 5;
  const int g = lane / 10;
  const int gt = lane - 10 * g;
  if (g == 3) return;
  const int gi = blockIdx.x * 30 + warp * 3 + g;
  if (gi >= NN) return;
  const int dst = g_order[gi];
  const unsigned mask = 0x3FFu << (10 * g);
  const int base = 10 * g;

  const int ha = (4 * gt) / 10;
  const int hb = (4 * gt + 3) / 10;
  const int m = 10 * (ha + 1) - 4 * gt;  // comps j>=m belong to head hb

  const float ad = (gt < 4) ? g_adst[dst * 8 + gt] : 0.f;
  float den = 0.f;
  float4 acc = make_float4(0.f, 0.f, 0.f, 0.f);

  const int row0 = g_rowstart[dst], row1 = g_rowstart[dst + 1];
  int sIdx = (row0 < row1) ? __ldg(&g_csr_src[row0]) : 0;
  float sc = (gt < 4) ? __ldg(&g_asrc[dst * 8 + gt]) : 0.f;
  float4 v = __ldg(reinterpret_cast<const float4*>(&g_xw[dst * 40 + 4 * gt]));
  for (int e = row0; ; e++) {
    const bool more = (e < row1);
    const int sIdx2 = (e + 1 < row1) ? __ldg(&g_csr_src[e + 1]) : 0;
    const float scN = (gt < 4) ? __ldg(&g_asrc[sIdx * 8 + gt]) : 0.f;
    const float4 vN = __ldg(reinterpret_cast<const float4*>(&g_xw[sIdx * 40 + 4 * gt]));
    float w = 0.f;
    if (gt < 4) {
      w = __expf(lrelu(sc + ad));
      den += w;
    }
    const float wA = __shfl_sync(mask, w, base + ha);
    const float wB = __shfl_sync(mask, w, base + hb);
    acc.x += ((0 >= m) ? wB : wA) * v.x;
    acc.y += ((1 >= m) ? wB : wA) * v.y;
    acc.z += ((2 >= m) ? wB : wA) * v.z;
    acc.w += ((3 >= m) ? wB : wA) * v.w;
    if (!more) break;
    sc = scN;
    v = vN;
    sIdx = sIdx2;
  }
  float dA = __shfl_sync(mask, den, base + ha);
  float dB = __shfl_sync(mask, den, base + hb);

  float4 l = *reinterpret_cast<const float4*>(&g_lin[dst * 40 + 4 * gt]);
  float b0 = bias[4 * gt + 0], b1 = bias[4 * gt + 1];
  float b2 = bias[4 * gt + 2], b3 = bias[4 * gt + 3];
  float4 o;
  o.x = elu1(acc.x / ((0 >= m) ? dB : dA) + l.x + b0);
  o.y = elu1(acc.y / ((1 >= m) ? dB : dA) + l.y + b1);
  o.z = elu1(acc.z / ((2 >= m) ? dB : dA) + l.z + b2);
  o.w = elu1(acc.w / ((3 >= m) ? dB : dA) + l.w + b3);
  *reinterpret_cast<float4*>(&g_h[dst * 40 + 4 * gt]) = o;
}

// ================= fused CSR aggregation, layer 3 (6 heads) =================
__global__ __launch_bounds__(320) void csr_agg_l3() {
  const int t = threadIdx.x;
  const int lane = t & 31, warp = t >> 5;
  const int g = lane / 10;
  const int gt = lane - 10 * g;
  if (g == 3) return;
  const int gi = blockIdx.x * 30 + warp * 3 + g;
  if (gi >= NN) return;
  const int dst = g_order[gi];
  const unsigned mask = 0x3FFu << (10 * g);
  const int base = 10 * g;

  const float ad = (gt < 6) ? g_adst[dst * 8 + gt] : 0.f;
  float den = 0.f;
  float4 acc[6];
#pragma unroll
  for (int h = 0; h < 6; h++) acc[h] = make_float4(0.f, 0.f, 0.f, 0.f);

  const int row0 = g_rowstart[dst], row1 = g_rowstart[dst + 1];
  int sIdx = (row0 < row1) ? __ldg(&g_csr_src[row0]) : 0;
  float sc = (gt < 6) ? __ldg(&g_asrc[dst * 8 + gt]) : 0.f;
  float4 v = __ldg(reinterpret_cast<const float4*>(&g_h[dst * 40 + 4 * gt]));
  for (int e = row0; ; e++) {
    const bool more = (e < row1);
    const int sIdx2 = (e + 1 < row1) ? __ldg(&g_csr_src[e + 1]) : 0;
    const float scN = (gt < 6) ? __ldg(&g_asrc[sIdx * 8 + gt]) : 0.f;
    const float4 vN = __ldg(reinterpret_cast<const float4*>(&g_h[sIdx * 40 + 4 * gt]));
    float w = 0.f;
    if (gt < 6) {
      w = __expf(lrelu(sc + ad));
      den += w;
    }
#pragma unroll
    for (int h = 0; h < 6; h++) {
      const float wh = __shfl_sync(mask, w, base + h);
      acc[h].x += wh * v.x;
      acc[h].y += wh * v.y;
      acc[h].z += wh * v.z;
      acc[h].w += wh * v.w;
    }
    if (!more) break;
    sc = scN;
    v = vN;
    sIdx = sIdx2;
  }
#pragma unroll
  for (int h = 0; h < 6; h++) {
    float dh = __shfl_sync(mask, den, base + h);
    float inv = 1.f / dh;
    float4 o = make_float4(acc[h].x * inv, acc[h].y * inv, acc[h].z * inv, acc[h].w * inv);
    *reinterpret_cast<float4*>(&g_aggs[dst * 240 + h * 40 + 4 * gt]) = o;
  }
}

// ---------------- layer 3 prep (merged: weights + score vectors) ----------------
__global__ void l3_prep_w(const float* __restrict__ W3, const float* __restrict__ lw3,
                          const float* __restrict__ b3, const float* __restrict__ lb3,
                          const float* __restrict__ as3, const float* __restrict__ ad3) {
  int i = blockIdx.x * 256 + threadIdx.x;
  if (i < 280 * 128) {
    int r = i / 128, c = i % 128;
    float v = 0.f;
    if (c < 121)
      v = (r < 240) ? W3[(r % 40) * 726 + (r / 40) * 121 + c] * (1.f / 6.f)
                    : lw3[(r - 240) * 121 + c];
    g_wm[i] = v;
  }
  if (i < 128) g_biasc[i] = (i < 121) ? b3[i] + lb3[i] : 0.f;
  if (blockIdx.x == 139 && threadIdx.x < 240) {
    int t = threadIdx.x;
    int h = t / 40, k = t % 40;
    float s = 0.f, d = 0.f;
    for (int c = 0; c < 121; c++) {
      float w = W3[k * 726 + h * 121 + c];
      s += w * as3[h * 121 + c];
      d += w * ad3[h * 121 + c];
    }
    g_vsrc[t] = s;
    g_vdst[t] = d;
  }
}

__global__ __launch_bounds__(256) void l3_scores() {
  __shared__ float sVs[240], sVd[240];
  int t = threadIdx.x;
  if (t < 240) { sVs[t] = g_vsrc[t]; sVd[t] = g_vdst[t]; }
  __syncthreads();
  int n = blockIdx.x * 256 + t;
  if (n >= NN) return;
  float xr[40];
  const float4* hp = reinterpret_cast<const float4*>(&g_h[n * 40]);
#pragma unroll
  for (int j = 0; j < 10; j++) {
    float4 v = hp[j];
    xr[4 * j] = v.x; xr[4 * j + 1] = v.y; xr[4 * j + 2] = v.z; xr[4 * j + 3] = v.w;
  }
#pragma unroll
  for (int h = 0; h < 6; h++) {
    float s = 0.f, d = 0.f;
#pragma unroll
    for (int k = 0; k < 40; k++) { s += xr[k] * sVs[h * 40 + k]; d += xr[k] * sVd[h * 40 + k]; }
    g_asrc[n * 8 + h] = s;
    g_adst[n * 8 + h] = d;
  }
}

// ---------------- final fused GEMM: out = [aggs | h] @ Wm + biasc, f32x2 ----------------
__global__ __launch_bounds__(256, 2) void final_gemm(float* __restrict__ out) {
  __shared__ __align__(16) float sA[40][128];
  __shared__ __align__(16) float sB[40][128];
  const int t = threadIdx.x;
  const int bm = blockIdx.x * 128;
  const int ty = t >> 4, tx = t & 15;
  const int fr = t >> 1;              // fill row 0..127
  const int fk = (t & 1) * 20;        // fill k-segment 0 or 20
  const bool valid = (bm + fr) < NN;
  u64 acc[8][4];
#pragma unroll
  for (int i = 0; i < 8; i++)
#pragma unroll
    for (int j = 0; j < 4; j++) acc[i][j] = 0ULL;

  for (int kt = 0; kt < 280; kt += 40) {
    {
      const int row = bm + fr;
      const float* srcA = (kt < 240) ? &g_aggs[(valid ? row : 0) * 240 + kt]
                                     : &g_h[(valid ? row : 0) * 40];
#pragma unroll
      for (int q = 0; q < 5; q++) {
        float4 v = valid ? *reinterpret_cast<const float4*>(srcA + fk + 4 * q)
                         : make_float4(0.f, 0.f, 0.f, 0.f);
        const int kk = fk + 4 * q;
        sA[kk][fr] = v.x;
        sA[kk + 1][fr] = v.y;
        sA[kk + 2][fr] = v.z;
        sA[kk + 3][fr] = v.w;
      }
    }
#pragma unroll
    for (int q = 0; q < 5; q++) {
      const int idx = q * 256 + t;
      const int kk = idx >> 5, c4 = idx & 31;
      *reinterpret_cast<float4*>(&sB[kk][4 * c4]) =
          *reinterpret_cast<const float4*>(&g_wm[(kt + kk) * 128 + 4 * c4]);
    }
    __syncthreads();
#pragma unroll
    for (int kk = 0; kk < 40; kk++) {
      float a[8];
      u64 b[4];
#pragma unroll
      for (int i = 0; i < 8; i++) a[i] = sA[kk][ty * 8 + i];
      const u64* bp = reinterpret_cast<const u64*>(&sB[kk][tx * 8]);
#pragma unroll
      for (int j = 0; j < 4; j++) b[j] = bp[j];
#pragma unroll
      for (int i = 0; i < 8; i++) {
        u64 ap;
        asm("mov.b64 %0, {%1, %1};" : "=l"(ap) : "f"(a[i]));
#pragma unroll
        for (int j = 0; j < 4; j++)
          asm("fma.rn.f32x2 %0, %1, %2, %0;" : "+l"(acc[i][j]) : "l"(ap), "l"(b[j]));
      }
    }
    __syncthreads();
  }
#pragma unroll
  for (int i = 0; i < 8; i++) {
    int row = bm + ty * 8 + i;
    if (row >= NN) continue;
#pragma unroll
    for (int j = 0; j < 4; j++) {
      float lo, hi;
      asm("mov.b64 {%0, %1}, %2;" : "=f"(lo), "=f"(hi) : "l"(acc[i][j]));
      int c0 = tx * 8 + 2 * j;
      if (c0 < 121) out[row * 121 + c0] = lo + g_biasc[c0];
      if (c0 + 1 < 121) out[row * 121 + c0 + 1] = hi + g_biasc[c0 + 1];
    }
  }
}

// ---------------- launch ----------------
extern "C" void kernel_launch(void* const* d_in, const int* in_sizes, int n_in,
                              void* d_out, int out_size) {
  const float* x   = (const float*)d_in[0];
  const int*   ei  = (const int*)d_in[1];
  const float* W1  = (const float*)d_in[2];
  const float* as1 = (const float*)d_in[3];
  const float* ad1 = (const float*)d_in[4];
  const float* b1  = (const float*)d_in[5];
  const float* lw1 = (const float*)d_in[6];
  const float* lb1 = (const float*)d_in[7];
  const float* W2  = (const float*)d_in[8];
  const float* as2 = (const float*)d_in[9];
  const float* ad2 = (const float*)d_in[10];
  const float* b2  = (const float*)d_in[11];
  const float* lw2 = (const float*)d_in[12];
  const float* lb2 = (const float*)d_in[13];
  const float* W3  = (const float*)d_in[14];
  const float* as3 = (const float*)d_in[15];
  const float* ad3 = (const float*)d_in[16];
  const float* b3  = (const float*)d_in[17];
  const float* lw3 = (const float*)d_in[18];
  const float* lb3 = (const float*)d_in[19];
  float* out = (float*)d_out;

  float* hbuf = nullptr;
  cudaGetSymbolAddress((void**)&hbuf, g_h);

  const int EB = EE / 256;            // 6250 exact
  const int NB = (NN + 255) / 256;    // 391
  const int GB = (NN + 29) / 30;      // 3334 groups-of-30 blocks
  const int SB = (NN + 511) / 512;    // 196

  // CSR build + degree sort (per launch; deterministic per-node results)
  zero_deg<<<NB, 256>>>();
  hist_k<<<EB, 256>>>(ei);
  dhist_k<<<NB, 256>>>();
  dscan_k<<<1, 256>>>();
  dscatter_k<<<NB, 256>>>();
  scan1_k<<<SB, 512>>>();
  scan2_k<<<1, 256>>>(SB);
  scan3_k<<<NB, 256>>>();
  scatter_k<<<EB, 256>>>(ei);

  // layer 1
  node_gemm_k<50><<<NN / 32, 128>>>(x, W1, lw1, lb1, as1, ad1);
  csr_agg_l12<<<GB, 320>>>(b1);
  // layer 2
  node_gemm_k<40><<<NN / 32, 128>>>(hbuf, W2, lw2, lb2, as2, ad2);
  csr_agg_l12<<<GB, 320>>>(b2);
  // layer 3
  l3_prep_w<<<140, 256>>>(W3, lw3, b3, lb3, as3, ad3);
  l3_scores<<<NB, 256>>>();
  csr_agg_l3<<<GB, 320>>>();
  final_gemm<<<(NN + 127) / 128, 256>>>(out);
}

// round 11
// speedup vs baseline: 1.0043x; 1.0043x over previous
#include <cuda_runtime.h>

#define NN 100000
#define EE 1600000

typedef unsigned long long u64;

// ---------------- scratch (static __device__, no allocation) ----------------
__device__ float g_xw[NN * 40];      // per-layer xw (concat heads)
__device__ float g_lin[NN * 40];     // skip linear output (incl lb)
__device__ float g_h[NN * 40];       // current hidden state
__device__ float g_asrc[NN * 8];     // per-head src scores (padded to 8)
__device__ float g_adst[NN * 8];
__device__ float g_aggs[NN * 240];   // layer-3 per-head aggregated h2 [N,6,40]
__device__ float g_vsrc[240];        // W3[:,h,:]@as3[h]  -> [6,40]
__device__ float g_vdst[240];
__device__ float g_wm[280 * 128];    // fused final weight [280,128pad]
__device__ float g_biasc[128];       // b3 + lb3

// CSR scratch
__device__ int g_deg[NN];
__device__ int g_incl[NN];
__device__ int g_bsum[256];
__device__ int g_boff[256];
__device__ int g_rowstart[NN + 1];
__device__ int g_cursor[NN];
__device__ int g_csr_src[EE];

__device__ __forceinline__ float lrelu(float v) { return v > 0.f ? v : 0.2f * v; }
__device__ __forceinline__ float elu1(float v) { return v > 0.f ? v : (__expf(v) - 1.f); }

// ================= CSR build =================
__global__ void zero_deg() {
  int i = blockIdx.x * 256 + threadIdx.x;
  if (i < NN) g_deg[i] = 0;
}
__global__ void hist_k(const int* __restrict__ ei) {
  int e = blockIdx.x * 256 + threadIdx.x;
  if (e < EE) atomicAdd(&g_deg[ei[EE + e]], 1);
}
__global__ void scan1_k() {  // 196 blocks x 512
  __shared__ int sb[512];
  int t = threadIdx.x;
  int i = blockIdx.x * 512 + t;
  int v = (i < NN) ? g_deg[i] : 0;
  sb[t] = v;
  __syncthreads();
  for (int off = 1; off < 512; off <<= 1) {
    int x = (t >= off) ? sb[t - off] : 0;
    __syncthreads();
    sb[t] += x;
    __syncthreads();
  }
  if (i < NN) g_incl[i] = sb[t];
  if (t == 511) g_bsum[blockIdx.x] = sb[511];
}
__global__ void scan2_k(int nb) {  // 1 block, 256 threads
  __shared__ int sb[256];
  int t = threadIdx.x;
  int own = (t < nb) ? g_bsum[t] : 0;
  sb[t] = own;
  __syncthreads();
  for (int off = 1; off < 256; off <<= 1) {
    int x = (t >= off) ? sb[t - off] : 0;
    __syncthreads();
    sb[t] += x;
    __syncthreads();
  }
  g_boff[t] = sb[t] - own;  // exclusive
}
__global__ void scan3_k() {
  int i = blockIdx.x * 256 + threadIdx.x;
  if (i < NN) {
    int rs = g_incl[i] - g_deg[i] + g_boff[i / 512];
    g_rowstart[i] = rs;
    g_cursor[i] = rs;
    if (i == NN - 1) g_rowstart[NN] = EE;
  }
}
__global__ void scatter_k(const int* __restrict__ ei) {
  int e = blockIdx.x * 256 + threadIdx.x;
  if (e < EE) {
    int s = ei[e], d = ei[EE + e];
    int p = atomicAdd(&g_cursor[d], 1);
    g_csr_src[p] = s;
  }
}

// ---------------- node GEMM: xw = x@W, lin = x@lw+lb, scores ----
template <int KDIM>
__global__ __launch_bounds__(128) void node_gemm_k(
    const float* __restrict__ x, const float* __restrict__ W,
    const float* __restrict__ lw, const float* __restrict__ lb,
    const float* __restrict__ as_, const float* __restrict__ ad_) {
  __shared__ float sW[KDIM * 80];
  __shared__ float sX[32 * (KDIM + 1)];
  __shared__ float sAs[40], sAd[40], sLb[40];
  const int t = threadIdx.x;
  for (int i = t; i < KDIM * 80; i += 128) {
    int k = i / 80, j = i % 80;
    sW[i] = (j < 40) ? W[k * 40 + j] : lw[k * 40 + (j - 40)];
  }
  const int nb = blockIdx.x * 32;
  for (int i = t; i < 32 * KDIM; i += 128) {
    int r = i / KDIM, k = i % KDIM;
    sX[r * (KDIM + 1) + k] = x[(nb + r) * KDIM + k];
  }
  if (t < 40) { sAs[t] = as_[t]; sAd[t] = ad_[t]; sLb[t] = lb[t]; }
  __syncthreads();

  const int row = t >> 2, cg = t & 3, c0 = cg * 20;
  float acc[20];
#pragma unroll
  for (int j = 0; j < 20; j++) acc[j] = 0.f;
#pragma unroll 5
  for (int k = 0; k < KDIM; k++) {
    float a = sX[row * (KDIM + 1) + k];
    const float4* w4 = reinterpret_cast<const float4*>(&sW[k * 80 + c0]);
#pragma unroll
    for (int q = 0; q < 5; q++) {
      float4 w = w4[q];
      acc[4 * q + 0] += a * w.x;
      acc[4 * q + 1] += a * w.y;
      acc[4 * q + 2] += a * w.z;
      acc[4 * q + 3] += a * w.w;
    }
  }
  const int n = nb + row;
  if (cg < 2) {
    float4* o = reinterpret_cast<float4*>(&g_xw[n * 40 + c0]);
#pragma unroll
    for (int q = 0; q < 5; q++)
      o[q] = make_float4(acc[4 * q], acc[4 * q + 1], acc[4 * q + 2], acc[4 * q + 3]);
    float s0 = 0.f, s1 = 0.f, d0 = 0.f, d1 = 0.f;
#pragma unroll
    for (int j = 0; j < 10; j++) {
      s0 += acc[j] * sAs[c0 + j];           d0 += acc[j] * sAd[c0 + j];
      s1 += acc[10 + j] * sAs[c0 + 10 + j]; d1 += acc[10 + j] * sAd[c0 + 10 + j];
    }
    const int h0 = 2 * cg;
    g_asrc[n * 8 + h0] = s0;      g_asrc[n * 8 + h0 + 1] = s1;
    g_adst[n * 8 + h0] = d0;      g_adst[n * 8 + h0 + 1] = d1;
  } else {
    const int lc = c0 - 40;
    float4* o = reinterpret_cast<float4*>(&g_lin[n * 40 + lc]);
#pragma unroll
    for (int q = 0; q < 5; q++)
      o[q] = make_float4(acc[4 * q] + sLb[lc + 4 * q], acc[4 * q + 1] + sLb[lc + 4 * q + 1],
                         acc[4 * q + 2] + sLb[lc + 4 * q + 2], acc[4 * q + 3] + sLb[lc + 4 * q + 3]);
  }
}

// ================= fused CSR aggregation, layers 1/2 (4 heads) =================
// 10-lane groups, 3 per warp, sequential dst. Items = self-loop + CSR edges.
// Unrolled x2: two items per iteration, pipelined one pair ahead (6 LDGs in
// flight per group). Invalid second item contributes w=0 (no divergence).
__global__ __launch_bounds__(320) void csr_agg_l12(const float* __restrict__ bias) {
  const int t = threadIdx.x;
  const int lane = t & 31, warp = t >> 5;
  const int g = lane / 10;
  const int gt = lane - 10 * g;
  if (g == 3) return;
  const int dst = blockIdx.x * 30 + warp * 3 + g;
  if (dst >= NN) return;
  const unsigned mask = 0x3FFu << (10 * g);
  const int base = 10 * g;

  const int ha = (4 * gt) / 10;
  const int hb = (4 * gt + 3) / 10;
  const int m = 10 * (ha + 1) - 4 * gt;  // comps j>=m belong to head hb

  const float ad = (gt < 4) ? g_adst[dst * 8 + gt] : 0.f;
  float den = 0.f;
  float4 acc = make_float4(0.f, 0.f, 0.f, 0.f);

  const int row0 = g_rowstart[dst], row1 = g_rowstart[dst + 1];
  const int total = row1 - row0 + 1;  // self-loop is item 0

  int s0 = dst;
  int s1 = (1 < total) ? __ldg(&g_csr_src[row0]) : dst;
  float sc0 = (gt < 4) ? __ldg(&g_asrc[s0 * 8 + gt]) : 0.f;
  float sc1 = (gt < 4) ? __ldg(&g_asrc[s1 * 8 + gt]) : 0.f;
  float4 v0 = __ldg(reinterpret_cast<const float4*>(&g_xw[s0 * 40 + 4 * gt]));
  float4 v1 = __ldg(reinterpret_cast<const float4*>(&g_xw[s1 * 40 + 4 * gt]));
  bool val1 = (1 < total);

  for (int i = 0; ; i += 2) {
    const bool more = (i + 2 < total);
    const int n0 = (i + 2 < total) ? __ldg(&g_csr_src[row0 + i + 1]) : 0;
    const int n1 = (i + 3 < total) ? __ldg(&g_csr_src[row0 + i + 2]) : 0;
    const float nsc0 = (gt < 4) ? __ldg(&g_asrc[n0 * 8 + gt]) : 0.f;
    const float nsc1 = (gt < 4) ? __ldg(&g_asrc[n1 * 8 + gt]) : 0.f;
    const float4 nv0 = __ldg(reinterpret_cast<const float4*>(&g_xw[n0 * 40 + 4 * gt]));
    const float4 nv1 = __ldg(reinterpret_cast<const float4*>(&g_xw[n1 * 40 + 4 * gt]));

    float w0 = 0.f, w1 = 0.f;
    if (gt < 4) {
      w0 = __expf(lrelu(sc0 + ad));
      w1 = val1 ? __expf(lrelu(sc1 + ad)) : 0.f;
      den += w0 + w1;
    }
    const float w0A = __shfl_sync(mask, w0, base + ha);
    const float w0B = __shfl_sync(mask, w0, base + hb);
    const float w1A = __shfl_sync(mask, w1, base + ha);
    const float w1B = __shfl_sync(mask, w1, base + hb);
    acc.x += ((0 >= m) ? w0B : w0A) * v0.x + ((0 >= m) ? w1B : w1A) * v1.x;
    acc.y += ((1 >= m) ? w0B : w0A) * v0.y + ((1 >= m) ? w1B : w1A) * v1.y;
    acc.z += ((2 >= m) ? w0B : w0A) * v0.z + ((2 >= m) ? w1B : w1A) * v1.z;
    acc.w += ((3 >= m) ? w0B : w0A) * v0.w + ((3 >= m) ? w1B : w1A) * v1.w;
    if (!more) break;
    s0 = n0; s1 = n1;
    sc0 = nsc0; sc1 = nsc1;
    v0 = nv0; v1 = nv1;
    val1 = (i + 3 < total);
  }
  float dA = __shfl_sync(mask, den, base + ha);
  float dB = __shfl_sync(mask, den, base + hb);

  float4 l = *reinterpret_cast<const float4*>(&g_lin[dst * 40 + 4 * gt]);
  float b0 = bias[4 * gt + 0], b1 = bias[4 * gt + 1];
  float b2 = bias[4 * gt + 2], b3 = bias[4 * gt + 3];
  float4 o;
  o.x = elu1(acc.x / ((0 >= m) ? dB : dA) + l.x + b0);
  o.y = elu1(acc.y / ((1 >= m) ? dB : dA) + l.y + b1);
  o.z = elu1(acc.z / ((2 >= m) ? dB : dA) + l.z + b2);
  o.w = elu1(acc.w / ((3 >= m) ? dB : dA) + l.w + b3);
  *reinterpret_cast<float4*>(&g_h[dst * 40 + 4 * gt]) = o;
}

// ================= fused CSR aggregation, layer 3 (6 heads) =================
// Same x2-unrolled pipelined structure; lane gt owns float4 slice gt of h,
// accumulated for all 6 heads into a single register bank.
__global__ __launch_bounds__(320) void csr_agg_l3() {
  const int t = threadIdx.x;
  const int lane = t & 31, warp = t >> 5;
  const int g = lane / 10;
  const int gt = lane - 10 * g;
  if (g == 3) return;
  const int dst = blockIdx.x * 30 + warp * 3 + g;
  if (dst >= NN) return;
  const unsigned mask = 0x3FFu << (10 * g);
  const int base = 10 * g;

  const float ad = (gt < 6) ? g_adst[dst * 8 + gt] : 0.f;
  float den = 0.f;
  float4 acc[6];
#pragma unroll
  for (int h = 0; h < 6; h++) acc[h] = make_float4(0.f, 0.f, 0.f, 0.f);

  const int row0 = g_rowstart[dst], row1 = g_rowstart[dst + 1];
  const int total = row1 - row0 + 1;

  int s0 = dst;
  int s1 = (1 < total) ? __ldg(&g_csr_src[row0]) : dst;
  float sc0 = (gt < 6) ? __ldg(&g_asrc[s0 * 8 + gt]) : 0.f;
  float sc1 = (gt < 6) ? __ldg(&g_asrc[s1 * 8 + gt]) : 0.f;
  float4 v0 = __ldg(reinterpret_cast<const float4*>(&g_h[s0 * 40 + 4 * gt]));
  float4 v1 = __ldg(reinterpret_cast<const float4*>(&g_h[s1 * 40 + 4 * gt]));
  bool val1 = (1 < total);

  for (int i = 0; ; i += 2) {
    const bool more = (i + 2 < total);
    const int n0 = (i + 2 < total) ? __ldg(&g_csr_src[row0 + i + 1]) : 0;
    const int n1 = (i + 3 < total) ? __ldg(&g_csr_src[row0 + i + 2]) : 0;
    const float nsc0 = (gt < 6) ? __ldg(&g_asrc[n0 * 8 + gt]) : 0.f;
    const float nsc1 = (gt < 6) ? __ldg(&g_asrc[n1 * 8 + gt]) : 0.f;
    const float4 nv0 = __ldg(reinterpret_cast<const float4*>(&g_h[n0 * 40 + 4 * gt]));
    const float4 nv1 = __ldg(reinterpret_cast<const float4*>(&g_h[n1 * 40 + 4 * gt]));

    float w0 = 0.f, w1 = 0.f;
    if (gt < 6) {
      w0 = __expf(lrelu(sc0 + ad));
      w1 = val1 ? __expf(lrelu(sc1 + ad)) : 0.f;
      den += w0 + w1;
    }
#pragma unroll
    for (int h = 0; h < 6; h++) {
      const float wh0 = __shfl_sync(mask, w0, base + h);
      const float wh1 = __shfl_sync(mask, w1, base + h);
      acc[h].x += wh0 * v0.x + wh1 * v1.x;
      acc[h].y += wh0 * v0.y + wh1 * v1.y;
      acc[h].z += wh0 * v0.z + wh1 * v1.z;
      acc[h].w += wh0 * v0.w + wh1 * v1.w;
    }
    if (!more) break;
    s0 = n0; s1 = n1;
    sc0 = nsc0; sc1 = nsc1;
    v0 = nv0; v1 = nv1;
    val1 = (i + 3 < total);
  }
#pragma unroll
  for (int h = 0; h < 6; h++) {
    float dh = __shfl_sync(mask, den, base + h);
    float inv = 1.f / dh;
    float4 o = make_float4(acc[h].x * inv, acc[h].y * inv, acc[h].z * inv, acc[h].w * inv);
    *reinterpret_cast<float4*>(&g_aggs[dst * 240 + h * 40 + 4 * gt]) = o;
  }
}

// ---------------- layer 3 prep (merged: weights + score vectors) ----------------
__global__ void l3_prep_w(const float* __restrict__ W3, const float* __restrict__ lw3,
                          const float* __restrict__ b3, const float* __restrict__ lb3,
                          const float* __restrict__ as3, const float* __restrict__ ad3) {
  int i = blockIdx.x * 256 + threadIdx.x;
  if (i < 280 * 128) {
    int r = i / 128, c = i % 128;
    float v = 0.f;
    if (c < 121)
      v = (r < 240) ? W3[(r % 40) * 726 + (r / 40) * 121 + c] * (1.f / 6.f)
                    : lw3[(r - 240) * 121 + c];
    g_wm[i] = v;
  }
  if (i < 128) g_biasc[i] = (i < 121) ? b3[i] + lb3[i] : 0.f;
  if (blockIdx.x == 139 && threadIdx.x < 240) {
    int t = threadIdx.x;
    int h = t / 40, k = t % 40;
    float s = 0.f, d = 0.f;
    for (int c = 0; c < 121; c++) {
      float w = W3[k * 726 + h * 121 + c];
      s += w * as3[h * 121 + c];
      d += w * ad3[h * 121 + c];
    }
    g_vsrc[t] = s;
    g_vdst[t] = d;
  }
}

__global__ __launch_bounds__(256) void l3_scores() {
  __shared__ float sVs[240], sVd[240];
  int t = threadIdx.x;
  if (t < 240) { sVs[t] = g_vsrc[t]; sVd[t] = g_vdst[t]; }
  __syncthreads();
  int n = blockIdx.x * 256 + t;
  if (n >= NN) return;
  float xr[40];
  const float4* hp = reinterpret_cast<const float4*>(&g_h[n * 40]);
#pragma unroll
  for (int j = 0; j < 10; j++) {
    float4 v = hp[j];
    xr[4 * j] = v.x; xr[4 * j + 1] = v.y; xr[4 * j + 2] = v.z; xr[4 * j + 3] = v.w;
  }
#pragma unroll
  for (int h = 0; h < 6; h++) {
    float s = 0.f, d = 0.f;
#pragma unroll
    for (int k = 0; k < 40; k++) { s += xr[k] * sVs[h * 40 + k]; d += xr[k] * sVd[h * 40 + k]; }
    g_asrc[n * 8 + h] = s;
    g_adst[n * 8 + h] = d;
  }
}

// ---------------- final fused GEMM: out = [aggs | h] @ Wm + biasc, f32x2 ----------------
__global__ __launch_bounds__(256, 2) void final_gemm(float* __restrict__ out) {
  __shared__ __align__(16) float sA[40][128];
  __shared__ __align__(16) float sB[40][128];
  const int t = threadIdx.x;
  const int bm = blockIdx.x * 128;
  const int ty = t >> 4, tx = t & 15;
  const int fr = t >> 1;              // fill row 0..127
  const int fk = (t & 1) * 20;        // fill k-segment 0 or 20
  const bool valid = (bm + fr) < NN;
  u64 acc[8][4];
#pragma unroll
  for (int i = 0; i < 8; i++)
#pragma unroll
    for (int j = 0; j < 4; j++) acc[i][j] = 0ULL;

  for (int kt = 0; kt < 280; kt += 40) {
    {
      const int row = bm + fr;
      const float* srcA = (kt < 240) ? &g_aggs[(valid ? row : 0) * 240 + kt]
                                     : &g_h[(valid ? row : 0) * 40];
#pragma unroll
      for (int q = 0; q < 5; q++) {
        float4 v = valid ? *reinterpret_cast<const float4*>(srcA + fk + 4 * q)
                         : make_float4(0.f, 0.f, 0.f, 0.f);
        const int kk = fk + 4 * q;
        sA[kk][fr] = v.x;
        sA[kk + 1][fr] = v.y;
        sA[kk + 2][fr] = v.z;
        sA[kk + 3][fr] = v.w;
      }
    }
#pragma unroll
    for (int q = 0; q < 5; q++) {
      const int idx = q * 256 + t;
      const int kk = idx >> 5, c4 = idx & 31;
      *reinterpret_cast<float4*>(&sB[kk][4 * c4]) =
          *reinterpret_cast<const float4*>(&g_wm[(kt + kk) * 128 + 4 * c4]);
    }
    __syncthreads();
#pragma unroll
    for (int kk = 0; kk < 40; kk++) {
      float a[8];
      u64 b[4];
#pragma unroll
      for (int i = 0; i < 8; i++) a[i] = sA[kk][ty * 8 + i];
      const u64* bp = reinterpret_cast<const u64*>(&sB[kk][tx * 8]);
#pragma unroll
      for (int j = 0; j < 4; j++) b[j] = bp[j];
#pragma unroll
      for (int i = 0; i < 8; i++) {
        u64 ap;
        asm("mov.b64 %0, {%1, %1};" : "=l"(ap) : "f"(a[i]));
#pragma unroll
        for (int j = 0; j < 4; j++)
          asm("fma.rn.f32x2 %0, %1, %2, %0;" : "+l"(acc[i][j]) : "l"(ap), "l"(b[j]));
      }
    }
    __syncthreads();
  }
#pragma unroll
  for (int i = 0; i < 8; i++) {
    int row = bm + ty * 8 + i;
    if (row >= NN) continue;
#pragma unroll
    for (int j = 0; j < 4; j++) {
      float lo, hi;
      asm("mov.b64 {%0, %1}, %2;" : "=f"(lo), "=f"(hi) : "l"(acc[i][j]));
      int c0 = tx * 8 + 2 * j;
      if (c0 < 121) out[row * 121 + c0] = lo + g_biasc[c0];
      if (c0 + 1 < 121) out[row * 121 + c0 + 1] = hi + g_biasc[c0 + 1];
    }
  }
}

// ---------------- launch ----------------
extern "C" void kernel_launch(void* const* d_in, const int* in_sizes, int n_in,
                              void* d_out, int out_size) {
  const float* x   = (const float*)d_in[0];
  const int*   ei  = (const int*)d_in[1];
  const float* W1  = (const float*)d_in[2];
  const float* as1 = (const float*)d_in[3];
  const float* ad1 = (const float*)d_in[4];
  const float* b1  = (const float*)d_in[5];
  const float* lw1 = (const float*)d_in[6];
  const float* lb1 = (const float*)d_in[7];
  const float* W2  = (const float*)d_in[8];
  const float* as2 = (const float*)d_in[9];
  const float* ad2 = (const float*)d_in[10];
  const float* b2  = (const float*)d_in[11];
  const float* lw2 = (const float*)d_in[12];
  const float* lb2 = (const float*)d_in[13];
  const float* W3  = (const float*)d_in[14];
  const float* as3 = (const float*)d_in[15];
  const float* ad3 = (const float*)d_in[16];
  const float* b3  = (const float*)d_in[17];
  const float* lw3 = (const float*)d_in[18];
  const float* lb3 = (const float*)d_in[19];
  float* out = (float*)d_out;

  float* hbuf = nullptr;
  cudaGetSymbolAddress((void**)&hbuf, g_h);

  const int EB = EE / 256;            // 6250 exact
  const int NB = (NN + 255) / 256;    // 391
  const int GB = (NN + 29) / 30;      // 3334 groups-of-30 blocks
  const int SB = (NN + 511) / 512;    // 196

  // CSR build (per launch; deterministic per-node results)
  zero_deg<<<NB, 256>>>();
  hist_k<<<EB, 256>>>(ei);
  scan1_k<<<SB, 512>>>();
  scan2_k<<<1, 256>>>(SB);
  scan3_k<<<NB, 256>>>();
  scatter_k<<<EB, 256>>>(ei);

  // layer 1
  node_gemm_k<50><<<NN / 32, 128>>>(x, W1, lw1, lb1, as1, ad1);
  csr_agg_l12<<<GB, 320>>>(b1);
  // layer 2
  node_gemm_k<40><<<NN / 32, 128>>>(hbuf, W2, lw2, lb2, as2, ad2);
  csr_agg_l12<<<GB, 320>>>(b2);
  // layer 3
  l3_prep_w<<<140, 256>>>(W3, lw3, b3, lb3, as3, ad3);
  l3_scores<<<NB, 256>>>();
  csr_agg_l3<<<GB, 320>>>();
  final_gemm<<<(NN + 127) / 128, 256>>>(out);
}

// round 12
// speedup vs baseline: 1.0697x; 1.0652x over previous
#include <cuda_runtime.h>

#define NN 100000
#define EE 1600000

typedef unsigned long long u64;

// ---------------- scratch (static __device__, no allocation) ----------------
__device__ float g_xw[NN * 40];      // per-layer xw (concat heads)
__device__ float g_lin[NN * 40];     // skip linear output (incl lb)
__device__ float g_h[NN * 40];       // current hidden state
__device__ float g_asrc[NN * 8];     // per-head src scores (padded to 8)
__device__ float g_adst[NN * 8];
__device__ float g_aggs[NN * 240];   // layer-3 per-head aggregated h2 [N,6,40]
__device__ float g_vsrc[240];        // W3[:,h,:]@as3[h]  -> [6,40]
__device__ float g_vdst[240];
__device__ float g_wm[280 * 128];    // fused final weight [280,128pad]
__device__ float g_biasc[128];       // b3 + lb3

// CSR scratch
__device__ int g_deg[NN];
__device__ int g_incl[NN];
__device__ int g_bsum[256];
__device__ int g_boff[256];
__device__ int g_rowstart[NN + 1];
__device__ int g_cursor[NN];
__device__ int g_csr_src[EE];

__device__ __forceinline__ float lrelu(float v) { return v > 0.f ? v : 0.2f * v; }
__device__ __forceinline__ float elu1(float v) { return v > 0.f ? v : (__expf(v) - 1.f); }

// ================= init: zero degrees  ∥  layer-3 weight prep =================
// blocks [0, NB): zero g_deg. blocks [NB, NB+140): build g_wm/g_biasc/g_vsrc/g_vdst.
__global__ __launch_bounds__(256) void init_k(
    int NB,
    const float* __restrict__ W3, const float* __restrict__ lw3,
    const float* __restrict__ b3, const float* __restrict__ lb3,
    const float* __restrict__ as3, const float* __restrict__ ad3) {
  if ((int)blockIdx.x < NB) {
    int i = blockIdx.x * 256 + threadIdx.x;
    if (i < NN) g_deg[i] = 0;
    return;
  }
  const int bb = blockIdx.x - NB;  // 0..139
  int i = bb * 256 + threadIdx.x;  // < 280*128 = 35840 exactly
  {
    int r = i / 128, c = i % 128;
    float v = 0.f;
    if (c < 121)
      v = (r < 240) ? W3[(r % 40) * 726 + (r / 40) * 121 + c] * (1.f / 6.f)
                    : lw3[(r - 240) * 121 + c];
    g_wm[i] = v;
  }
  if (i < 128) g_biasc[i] = (i < 121) ? b3[i] + lb3[i] : 0.f;
  if (bb == 139 && threadIdx.x < 240) {
    int t = threadIdx.x;
    int h = t / 40, k = t % 40;
    float s = 0.f, d = 0.f;
    for (int c = 0; c < 121; c++) {
      float w = W3[k * 726 + h * 121 + c];
      s += w * as3[h * 121 + c];
      d += w * ad3[h * 121 + c];
    }
    g_vsrc[t] = s;
    g_vdst[t] = d;
  }
}

// ================= fused: layer-1 node GEMM  ∥  dst-degree histogram =========
// blocks [0, 3125): node GEMM (KDIM=50, 32 nodes/block, 128 threads).
// blocks [3125, 3125+12500): histogram over edges (128 edges/block, exact).
__global__ __launch_bounds__(128) void gemm1_hist_k(
    const float* __restrict__ x, const float* __restrict__ W,
    const float* __restrict__ lw, const float* __restrict__ lb,
    const float* __restrict__ as_, const float* __restrict__ ad_,
    const int* __restrict__ ei) {
  const int t = threadIdx.x;
  if ((int)blockIdx.x >= 3125) {
    int e = (blockIdx.x - 3125) * 128 + t;  // 12500*128 == EE exactly
    atomicAdd(&g_deg[ei[EE + e]], 1);
    return;
  }
  const int KDIM = 50;
  __shared__ float sW[KDIM * 80];
  __shared__ float sX[32 * (KDIM + 1)];
  __shared__ float sAs[40], sAd[40], sLb[40];
  for (int i = t; i < KDIM * 80; i += 128) {
    int k = i / 80, j = i % 80;
    sW[i] = (j < 40) ? W[k * 40 + j] : lw[k * 40 + (j - 40)];
  }
  const int nb = blockIdx.x * 32;
  for (int i = t; i < 32 * KDIM; i += 128) {
    int r = i / KDIM, k = i % KDIM;
    sX[r * (KDIM + 1) + k] = x[(nb + r) * KDIM + k];
  }
  if (t < 40) { sAs[t] = as_[t]; sAd[t] = ad_[t]; sLb[t] = lb[t]; }
  __syncthreads();

  const int row = t >> 2, cg = t & 3, c0 = cg * 20;
  float acc[20];
#pragma unroll
  for (int j = 0; j < 20; j++) acc[j] = 0.f;
#pragma unroll 5
  for (int k = 0; k < KDIM; k++) {
    float a = sX[row * (KDIM + 1) + k];
    const float4* w4 = reinterpret_cast<const float4*>(&sW[k * 80 + c0]);
#pragma unroll
    for (int q = 0; q < 5; q++) {
      float4 w = w4[q];
      acc[4 * q + 0] += a * w.x;
      acc[4 * q + 1] += a * w.y;
      acc[4 * q + 2] += a * w.z;
      acc[4 * q + 3] += a * w.w;
    }
  }
  const int n = nb + row;
  if (cg < 2) {
    float4* o = reinterpret_cast<float4*>(&g_xw[n * 40 + c0]);
#pragma unroll
    for (int q = 0; q < 5; q++)
      o[q] = make_float4(acc[4 * q], acc[4 * q + 1], acc[4 * q + 2], acc[4 * q + 3]);
    float s0 = 0.f, s1 = 0.f, d0 = 0.f, d1 = 0.f;
#pragma unroll
    for (int j = 0; j < 10; j++) {
      s0 += acc[j] * sAs[c0 + j];           d0 += acc[j] * sAd[c0 + j];
      s1 += acc[10 + j] * sAs[c0 + 10 + j]; d1 += acc[10 + j] * sAd[c0 + 10 + j];
    }
    const int h0 = 2 * cg;
    g_asrc[n * 8 + h0] = s0;      g_asrc[n * 8 + h0 + 1] = s1;
    g_adst[n * 8 + h0] = d0;      g_adst[n * 8 + h0 + 1] = d1;
  } else {
    const int lc = c0 - 40;
    float4* o = reinterpret_cast<float4*>(&g_lin[n * 40 + lc]);
#pragma unroll
    for (int q = 0; q < 5; q++)
      o[q] = make_float4(acc[4 * q] + sLb[lc + 4 * q], acc[4 * q + 1] + sLb[lc + 4 * q + 1],
                         acc[4 * q + 2] + sLb[lc + 4 * q + 2], acc[4 * q + 3] + sLb[lc + 4 * q + 3]);
  }
}

// ================= CSR scan + scatter =================
__global__ void scan1_k() {  // 196 blocks x 512
  __shared__ int sb[512];
  int t = threadIdx.x;
  int i = blockIdx.x * 512 + t;
  int v = (i < NN) ? g_deg[i] : 0;
  sb[t] = v;
  __syncthreads();
  for (int off = 1; off < 512; off <<= 1) {
    int x = (t >= off) ? sb[t - off] : 0;
    __syncthreads();
    sb[t] += x;
    __syncthreads();
  }
  if (i < NN) g_incl[i] = sb[t];
  if (t == 511) g_bsum[blockIdx.x] = sb[511];
}
__global__ void scan2_k(int nb) {  // 1 block, 256 threads
  __shared__ int sb[256];
  int t = threadIdx.x;
  int own = (t < nb) ? g_bsum[t] : 0;
  sb[t] = own;
  __syncthreads();
  for (int off = 1; off < 256; off <<= 1) {
    int x = (t >= off) ? sb[t - off] : 0;
    __syncthreads();
    sb[t] += x;
    __syncthreads();
  }
  g_boff[t] = sb[t] - own;  // exclusive
}
__global__ void scan3_k() {
  int i = blockIdx.x * 256 + threadIdx.x;
  if (i < NN) {
    int rs = g_incl[i] - g_deg[i] + g_boff[i / 512];
    g_rowstart[i] = rs;
    g_cursor[i] = rs;
    if (i == NN - 1) g_rowstart[NN] = EE;
  }
}
__global__ void scatter_k(const int* __restrict__ ei) {
  int e = blockIdx.x * 256 + threadIdx.x;
  if (e < EE) {
    int s = ei[e], d = ei[EE + e];
    int p = atomicAdd(&g_cursor[d], 1);
    g_csr_src[p] = s;
  }
}

// ---------------- node GEMM (layer 2): xw = h@W, lin = h@lw+lb, scores ----
template <int KDIM>
__global__ __launch_bounds__(128) void node_gemm_k(
    const float* __restrict__ x, const float* __restrict__ W,
    const float* __restrict__ lw, const float* __restrict__ lb,
    const float* __restrict__ as_, const float* __restrict__ ad_) {
  __shared__ float sW[KDIM * 80];
  __shared__ float sX[32 * (KDIM + 1)];
  __shared__ float sAs[40], sAd[40], sLb[40];
  const int t = threadIdx.x;
  for (int i = t; i < KDIM * 80; i += 128) {
    int k = i / 80, j = i % 80;
    sW[i] = (j < 40) ? W[k * 40 + j] : lw[k * 40 + (j - 40)];
  }
  const int nb = blockIdx.x * 32;
  for (int i = t; i < 32 * KDIM; i += 128) {
    int r = i / KDIM, k = i % KDIM;
    sX[r * (KDIM + 1) + k] = x[(nb + r) * KDIM + k];
  }
  if (t < 40) { sAs[t] = as_[t]; sAd[t] = ad_[t]; sLb[t] = lb[t]; }
  __syncthreads();

  const int row = t >> 2, cg = t & 3, c0 = cg * 20;
  float acc[20];
#pragma unroll
  for (int j = 0; j < 20; j++) acc[j] = 0.f;
#pragma unroll 5
  for (int k = 0; k < KDIM; k++) {
    float a = sX[row * (KDIM + 1) + k];
    const float4* w4 = reinterpret_cast<const float4*>(&sW[k * 80 + c0]);
#pragma unroll
    for (int q = 0; q < 5; q++) {
      float4 w = w4[q];
      acc[4 * q + 0] += a * w.x;
      acc[4 * q + 1] += a * w.y;
      acc[4 * q + 2] += a * w.z;
      acc[4 * q + 3] += a * w.w;
    }
  }
  const int n = nb + row;
  if (cg < 2) {
    float4* o = reinterpret_cast<float4*>(&g_xw[n * 40 + c0]);
#pragma unroll
    for (int q = 0; q < 5; q++)
      o[q] = make_float4(acc[4 * q], acc[4 * q + 1], acc[4 * q + 2], acc[4 * q + 3]);
    float s0 = 0.f, s1 = 0.f, d0 = 0.f, d1 = 0.f;
#pragma unroll
    for (int j = 0; j < 10; j++) {
      s0 += acc[j] * sAs[c0 + j];           d0 += acc[j] * sAd[c0 + j];
      s1 += acc[10 + j] * sAs[c0 + 10 + j]; d1 += acc[10 + j] * sAd[c0 + 10 + j];
    }
    const int h0 = 2 * cg;
    g_asrc[n * 8 + h0] = s0;      g_asrc[n * 8 + h0 + 1] = s1;
    g_adst[n * 8 + h0] = d0;      g_adst[n * 8 + h0 + 1] = d1;
  } else {
    const int lc = c0 - 40;
    float4* o = reinterpret_cast<float4*>(&g_lin[n * 40 + lc]);
#pragma unroll
    for (int q = 0; q < 5; q++)
      o[q] = make_float4(acc[4 * q] + sLb[lc + 4 * q], acc[4 * q + 1] + sLb[lc + 4 * q + 1],
                         acc[4 * q + 2] + sLb[lc + 4 * q + 2], acc[4 * q + 3] + sLb[lc + 4 * q + 3]);
  }
}

// ================= fused CSR aggregation, layers 1/2 (4 heads) =================
// R5 form: 10-lane groups, 3 per warp, 1-deep score/feature pipeline.
__global__ __launch_bounds__(320) void csr_agg_l12(const float* __restrict__ bias) {
  const int t = threadIdx.x;
  const int lane = t & 31, warp = t >> 5;
  const int g = lane / 10;
  const int gt = lane - 10 * g;
  if (g == 3) return;
  const int dst = blockIdx.x * 30 + warp * 3 + g;
  if (dst >= NN) return;
  const unsigned mask = 0x3FFu << (10 * g);
  const int base = 10 * g;

  const int ha = (4 * gt) / 10;
  const int hb = (4 * gt + 3) / 10;
  const int m = 10 * (ha + 1) - 4 * gt;  // comps j>=m belong to head hb

  const float ad = (gt < 4) ? g_adst[dst * 8 + gt] : 0.f;
  float den = 0.f;
  float4 acc = make_float4(0.f, 0.f, 0.f, 0.f);

  const int row0 = g_rowstart[dst], row1 = g_rowstart[dst + 1];
  float sc = (gt < 4) ? __ldg(&g_asrc[dst * 8 + gt]) : 0.f;
  float4 v = __ldg(reinterpret_cast<const float4*>(&g_xw[dst * 40 + 4 * gt]));
  for (int e = row0; ; e++) {
    const bool more = (e < row1);
    const int sNxt = more ? __ldg(&g_csr_src[e]) : 0;
    const float scN = (gt < 4) ? __ldg(&g_asrc[sNxt * 8 + gt]) : 0.f;
    const float4 vN = __ldg(reinterpret_cast<const float4*>(&g_xw[sNxt * 40 + 4 * gt]));
    float w = 0.f;
    if (gt < 4) {
      w = __expf(lrelu(sc + ad));
      den += w;
    }
    const float wA = __shfl_sync(mask, w, base + ha);
    const float wB = __shfl_sync(mask, w, base + hb);
    acc.x += ((0 >= m) ? wB : wA) * v.x;
    acc.y += ((1 >= m) ? wB : wA) * v.y;
    acc.z += ((2 >= m) ? wB : wA) * v.z;
    acc.w += ((3 >= m) ? wB : wA) * v.w;
    if (!more) break;
    sc = scN;
    v = vN;
  }
  float dA = __shfl_sync(mask, den, base + ha);
  float dB = __shfl_sync(mask, den, base + hb);

  float4 l = *reinterpret_cast<const float4*>(&g_lin[dst * 40 + 4 * gt]);
  float b0 = bias[4 * gt + 0], b1 = bias[4 * gt + 1];
  float b2 = bias[4 * gt + 2], b3 = bias[4 * gt + 3];
  float4 o;
  o.x = elu1(acc.x / ((0 >= m) ? dB : dA) + l.x + b0);
  o.y = elu1(acc.y / ((1 >= m) ? dB : dA) + l.y + b1);
  o.z = elu1(acc.z / ((2 >= m) ? dB : dA) + l.z + b2);
  o.w = elu1(acc.w / ((3 >= m) ? dB : dA) + l.w + b3);
  *reinterpret_cast<float4*>(&g_h[dst * 40 + 4 * gt]) = o;
}

// ================= fused CSR aggregation, layer 3 (6 heads) =================
__global__ __launch_bounds__(320) void csr_agg_l3() {
  const int t = threadIdx.x;
  const int lane = t & 31, warp = t >> 5;
  const int g = lane / 10;
  const int gt = lane - 10 * g;
  if (g == 3) return;
  const int dst = blockIdx.x * 30 + warp * 3 + g;
  if (dst >= NN) return;
  const unsigned mask = 0x3FFu << (10 * g);
  const int base = 10 * g;

  const float ad = (gt < 6) ? g_adst[dst * 8 + gt] : 0.f;
  float den = 0.f;
  float4 acc[6];
#pragma unroll
  for (int h = 0; h < 6; h++) acc[h] = make_float4(0.f, 0.f, 0.f, 0.f);

  const int row0 = g_rowstart[dst], row1 = g_rowstart[dst + 1];
  float sc = (gt < 6) ? __ldg(&g_asrc[dst * 8 + gt]) : 0.f;
  float4 v = __ldg(reinterpret_cast<const float4*>(&g_h[dst * 40 + 4 * gt]));
  for (int e = row0; ; e++) {
    const bool more = (e < row1);
    const int sNxt = more ? __ldg(&g_csr_src[e]) : 0;
    const float scN = (gt < 6) ? __ldg(&g_asrc[sNxt * 8 + gt]) : 0.f;
    const float4 vN = __ldg(reinterpret_cast<const float4*>(&g_h[sNxt * 40 + 4 * gt]));
    float w = 0.f;
    if (gt < 6) {
      w = __expf(lrelu(sc + ad));
      den += w;
    }
#pragma unroll
    for (int h = 0; h < 6; h++) {
      const float wh = __shfl_sync(mask, w, base + h);
      acc[h].x += wh * v.x;
      acc[h].y += wh * v.y;
      acc[h].z += wh * v.z;
      acc[h].w += wh * v.w;
    }
    if (!more) break;
    sc = scN;
    v = vN;
  }
#pragma unroll
  for (int h = 0; h < 6; h++) {
    float dh = __shfl_sync(mask, den, base + h);
    float inv = 1.f / dh;
    float4 o = make_float4(acc[h].x * inv, acc[h].y * inv, acc[h].z * inv, acc[h].w * inv);
    *reinterpret_cast<float4*>(&g_aggs[dst * 240 + h * 40 + 4 * gt]) = o;
  }
}

// ---------------- layer 3 node scores ----------------
__global__ __launch_bounds__(256) void l3_scores() {
  __shared__ float sVs[240], sVd[240];
  int t = threadIdx.x;
  if (t < 240) { sVs[t] = g_vsrc[t]; sVd[t] = g_vdst[t]; }
  __syncthreads();
  int n = blockIdx.x * 256 + t;
  if (n >= NN) return;
  float xr[40];
  const float4* hp = reinterpret_cast<const float4*>(&g_h[n * 40]);
#pragma unroll
  for (int j = 0; j < 10; j++) {
    float4 v = hp[j];
    xr[4 * j] = v.x; xr[4 * j + 1] = v.y; xr[4 * j + 2] = v.z; xr[4 * j + 3] = v.w;
  }
#pragma unroll
  for (int h = 0; h < 6; h++) {
    float s = 0.f, d = 0.f;
#pragma unroll
    for (int k = 0; k < 40; k++) { s += xr[k] * sVs[h * 40 + k]; d += xr[k] * sVd[h * 40 + k]; }
    g_asrc[n * 8 + h] = s;
    g_adst[n * 8 + h] = d;
  }
}

// ---------------- final fused GEMM: out = [aggs | h] @ Wm + biasc, f32x2 ----------------
__global__ __launch_bounds__(256, 2) void final_gemm(float* __restrict__ out) {
  __shared__ __align__(16) float sA[40][128];
  __shared__ __align__(16) float sB[40][128];
  const int t = threadIdx.x;
  const int bm = blockIdx.x * 128;
  const int ty = t >> 4, tx = t & 15;
  const int fr = t >> 1;              // fill row 0..127
  const int fk = (t & 1) * 20;        // fill k-segment 0 or 20
  const bool valid = (bm + fr) < NN;
  u64 acc[8][4];
#pragma unroll
  for (int i = 0; i < 8; i++)
#pragma unroll
    for (int j = 0; j < 4; j++) acc[i][j] = 0ULL;

  for (int kt = 0; kt < 280; kt += 40) {
    {
      const int row = bm + fr;
      const float* srcA = (kt < 240) ? &g_aggs[(valid ? row : 0) * 240 + kt]
                                     : &g_h[(valid ? row : 0) * 40];
#pragma unroll
      for (int q = 0; q < 5; q++) {
        float4 v = valid ? *reinterpret_cast<const float4*>(srcA + fk + 4 * q)
                         : make_float4(0.f, 0.f, 0.f, 0.f);
        const int kk = fk + 4 * q;
        sA[kk][fr] = v.x;
        sA[kk + 1][fr] = v.y;
        sA[kk + 2][fr] = v.z;
        sA[kk + 3][fr] = v.w;
      }
    }
#pragma unroll
    for (int q = 0; q < 5; q++) {
      const int idx = q * 256 + t;
      const int kk = idx >> 5, c4 = idx & 31;
      *reinterpret_cast<float4*>(&sB[kk][4 * c4]) =
          *reinterpret_cast<const float4*>(&g_wm[(kt + kk) * 128 + 4 * c4]);
    }
    __syncthreads();
#pragma unroll
    for (int kk = 0; kk < 40; kk++) {
      float a[8];
      u64 b[4];
#pragma unroll
      for (int i = 0; i < 8; i++) a[i] = sA[kk][ty * 8 + i];
      const u64* bp = reinterpret_cast<const u64*>(&sB[kk][tx * 8]);
#pragma unroll
      for (int j = 0; j < 4; j++) b[j] = bp[j];
#pragma unroll
      for (int i = 0; i < 8; i++) {
        u64 ap;
        asm("mov.b64 %0, {%1, %1};" : "=l"(ap) : "f"(a[i]));
#pragma unroll
        for (int j = 0; j < 4; j++)
          asm("fma.rn.f32x2 %0, %1, %2, %0;" : "+l"(acc[i][j]) : "l"(ap), "l"(b[j]));
      }
    }
    __syncthreads();
  }
#pragma unroll
  for (int i = 0; i < 8; i++) {
    int row = bm + ty * 8 + i;
    if (row >= NN) continue;
#pragma unroll
    for (int j = 0; j < 4; j++) {
      float lo, hi;
      asm("mov.b64 {%0, %1}, %2;" : "=f"(lo), "=f"(hi) : "l"(acc[i][j]));
      int c0 = tx * 8 + 2 * j;
      if (c0 < 121) out[row * 121 + c0] = lo + g_biasc[c0];
      if (c0 + 1 < 121) out[row * 121 + c0 + 1] = hi + g_biasc[c0 + 1];
    }
  }
}

// ---------------- launch ----------------
extern "C" void kernel_launch(void* const* d_in, const int* in_sizes, int n_in,
                              void* d_out, int out_size) {
  const float* x   = (const float*)d_in[0];
  const int*   ei  = (const int*)d_in[1];
  const float* W1  = (const float*)d_in[2];
  const float* as1 = (const float*)d_in[3];
  const float* ad1 = (const float*)d_in[4];
  const float* b1  = (const float*)d_in[5];
  const float* lw1 = (const float*)d_in[6];
  const float* lb1 = (const float*)d_in[7];
  const float* W2  = (const float*)d_in[8];
  const float* as2 = (const float*)d_in[9];
  const float* ad2 = (const float*)d_in[10];
  const float* b2  = (const float*)d_in[11];
  const float* lw2 = (const float*)d_in[12];
  const float* lb2 = (const float*)d_in[13];
  const float* W3  = (const float*)d_in[14];
  const float* as3 = (const float*)d_in[15];
  const float* ad3 = (const float*)d_in[16];
  const float* b3  = (const float*)d_in[17];
  const float* lw3 = (const float*)d_in[18];
  const float* lb3 = (const float*)d_in[19];
  float* out = (float*)d_out;

  float* hbuf = nullptr;
  cudaGetSymbolAddress((void**)&hbuf, g_h);

  const int EB = EE / 256;            // 6250 exact
  const int NB = (NN + 255) / 256;    // 391
  const int GB = (NN + 29) / 30;      // 3334 groups-of-30 blocks
  const int SB = (NN + 511) / 512;    // 196

  // init: zero degrees  ∥  layer-3 weight prep
  init_k<<<NB + 140, 256>>>(NB, W3, lw3, b3, lb3, as3, ad3);
  // layer-1 node GEMM  ∥  degree histogram
  gemm1_hist_k<<<3125 + 12500, 128>>>(x, W1, lw1, lb1, as1, ad1, ei);
  // CSR scan + scatter
  scan1_k<<<SB, 512>>>();
  scan2_k<<<1, 256>>>(SB);
  scan3_k<<<NB, 256>>>();
  scatter_k<<<EB, 256>>>(ei);

  // layer 1 aggregation
  csr_agg_l12<<<GB, 320>>>(b1);
  // layer 2
  node_gemm_k<40><<<NN / 32, 128>>>(hbuf, W2, lw2, lb2, as2, ad2);
  csr_agg_l12<<<GB, 320>>>(b2);
  // layer 3
  l3_scores<<<NB, 256>>>();
  csr_agg_l3<<<GB, 320>>>();
  final_gemm<<<(NN + 127) / 128, 256>>>(out);
}